// round 8
// baseline (speedup 1.0000x reference)
#include <cuda_runtime.h>
#include <math_constants.h>
#include <cstdint>

// VQ-VAE vector quantizer, GB300 (PTX sm_103). Round 8: DP4A screening with
// 2-pixel register blocking (halves smem crossbar bytes, the R7 bottleneck)
// + exact fp32 refinement. Single kernel, last-CTA loss finalize.
// inputs:  d_in[0] = inputs [64,64,32,32] fp32 NCHW, d_in[1] = emb_w [512,64] fp32
// output:  d_out fp32: loss[1] | out[4194304] NCHW | idx[65536]

#define DD        64
#define KK        512
#define NPIX      65536
#define BLOCK     256
#define PXT       2                     // pixels per thread
#define GRID      (NPIX / (BLOCK * PXT))   // 128 CTAs
#define OUT_ELEMS (NPIX * DD)

#define OFF_E    0                      // int8 codebook [512][64] = 32768 B
#define OFF_B    32768                  // [512] f32 ||e||^2
#define OFF_SCR  34816                  // 64 f32 scratch
#define OFF_MSK  35072                  // [512 px][17] u32 candidate masks
#define SMEM_TOTAL (OFF_MSK + BLOCK * PXT * 17 * 4)   // 69888 B

__device__ float g_part[GRID];
__device__ unsigned int g_cnt;          // zero-init; restored to 0 each run

__global__ __launch_bounds__(BLOCK, 1)
void vq_main(const float* __restrict__ in, const float* __restrict__ emb,
             float* __restrict__ out) {
    extern __shared__ char smem[];
    uint4*    Ecb = (uint4*)(smem + OFF_E);
    float*    sB  = (float*)(smem + OFF_B);
    float*    scr = (float*)(smem + OFF_SCR);
    uint32_t* msk = (uint32_t*)(smem + OFF_MSK);
    const int tid = threadIdx.x, wid = tid >> 5, lane = tid & 31;

    // ---- codebook prologue: thread t owns codes t and t+256 ----
    float mxe = 0.0f, L1em = 0.0f;
    #pragma unroll
    for (int h = 0; h < 2; h++) {
        const int k = tid + h * 256;
        const float* er = emb + k * DD;
        float Bk = 0.0f, L1e = 0.0f;
        #pragma unroll 8
        for (int d = 0; d < DD; d++) {
            float v = er[d];
            Bk = __fadd_rn(Bk, __fmul_rn(v, v));   // R1/R2-proven exact order
            float a = fabsf(v);
            L1e += a;
            mxe = fmaxf(mxe, a);
        }
        sB[k] = Bk;
        L1em = fmaxf(L1em, L1e);
    }
    float m1 = mxe, m2 = L1em;
    #pragma unroll
    for (int o = 16; o > 0; o >>= 1) {
        m1 = fmaxf(m1, __shfl_xor_sync(~0u, m1, o));
        m2 = fmaxf(m2, __shfl_xor_sync(~0u, m2, o));
    }
    if (lane == 0) { scr[wid] = m1; scr[8 + wid] = m2; }
    __syncthreads();
    float maxe = scr[0], L1emax = scr[8];
    #pragma unroll
    for (int w = 1; w < 8; w++) {
        maxe   = fmaxf(maxe,   scr[w]);
        L1emax = fmaxf(L1emax, scr[8 + w]);
    }
    maxe = fmaxf(maxe, 1e-30f);
    const float se = maxe * (1.0f / 127.0f);
    const float inv_se = 127.0f / maxe;
    #pragma unroll
    for (int h = 0; h < 2; h++) {
        const int k = tid + h * 256;
        const float* er = emb + k * DD;
        uint32_t* Erow = (uint32_t*)(Ecb + k * 4);
        #pragma unroll
        for (int i = 0; i < 16; i++) {
            int q0 = __float2int_rn(er[4 * i + 0] * inv_se);
            int q1 = __float2int_rn(er[4 * i + 1] * inv_se);
            int q2 = __float2int_rn(er[4 * i + 2] * inv_se);
            int q3 = __float2int_rn(er[4 * i + 3] * inv_se);
            Erow[i] = (uint32_t)(q0 & 0xFF) | ((uint32_t)(q1 & 0xFF) << 8) |
                      ((uint32_t)(q2 & 0xFF) << 16) | ((uint32_t)(q3 & 0xFF) << 24);
        }
    }
    __syncthreads();

    // ---- two pixels per thread: stats + int8 packing ----
    const int n0 = blockIdx.x * (BLOCK * PXT) + tid;          // and n0 + 256
    const float* px0 = in + (size_t)(n0 >> 10) * 65536 + (n0 & 1023);
    const int n1 = n0 + 256;
    const float* px1 = in + (size_t)(n1 >> 10) * 65536 + (n1 & 1023);

    float A0, A1, mg0, mg1, c20, c21;
    uint32_t X0[16], X1[16];
    #pragma unroll
    for (int h = 0; h < 2; h++) {
        const float* px = h ? px1 : px0;
        uint32_t* X = h ? X1 : X0;
        float a0 = 0.f, a1 = 0.f, a2 = 0.f, a3 = 0.f, L1x = 0.f, mxx = 0.f;
        #pragma unroll
        for (int d = 0; d < DD; d += 4) {
            float v0 = px[(size_t)(d + 0) << 10];
            float v1 = px[(size_t)(d + 1) << 10];
            float v2 = px[(size_t)(d + 2) << 10];
            float v3 = px[(size_t)(d + 3) << 10];
            a0 = __fadd_rn(a0, __fmul_rn(v0, v0));
            a1 = __fadd_rn(a1, __fmul_rn(v1, v1));
            a2 = __fadd_rn(a2, __fmul_rn(v2, v2));
            a3 = __fadd_rn(a3, __fmul_rn(v3, v3));
            L1x += fabsf(v0) + fabsf(v1) + fabsf(v2) + fabsf(v3);
            mxx = fmaxf(mxx, fmaxf(fmaxf(fabsf(v0), fabsf(v1)),
                                   fmaxf(fabsf(v2), fabsf(v3))));
        }
        float A = __fadd_rn(__fadd_rn(a0, a2), __fadd_rn(a1, a3));
        mxx = fmaxf(mxx, 1e-30f);
        float sx = mxx * (1.0f / 127.0f);
        float inv_sx = 127.0f / mxx;
        #pragma unroll
        for (int i = 0; i < 16; i++) {
            int q0 = __float2int_rn(px[(size_t)(4 * i + 0) << 10] * inv_sx);
            int q1 = __float2int_rn(px[(size_t)(4 * i + 1) << 10] * inv_sx);
            int q2 = __float2int_rn(px[(size_t)(4 * i + 2) << 10] * inv_sx);
            int q3 = __float2int_rn(px[(size_t)(4 * i + 3) << 10] * inv_sx);
            X[i] = (uint32_t)(q0 & 0xFF) | ((uint32_t)(q1 & 0xFF) << 8) |
                   ((uint32_t)(q2 & 0xFF) << 16) | ((uint32_t)(q3 & 0xFF) << 24);
        }
        float mg = sx * L1emax + se * L1x + 16.0f * sx * se + 1e-6f; // 2*delta
        if (h) { A1 = A; mg1 = mg; c21 = -2.0f * sx * se; }
        else   { A0 = A; mg0 = mg; c20 = -2.0f * sx * se; }
    }

    // ---- DP4A screening: one row load feeds both pixels ----
    float thr0 = CUDART_INF_F, thr1 = CUDART_INF_F;
    uint32_t* mrow0 = msk + tid * 17;
    uint32_t* mrow1 = msk + (256 + tid) * 17;
    #pragma unroll 1
    for (int w = 0; w < 16; w++) {
        uint32_t m0 = 0, m1w = 0;
        const uint4* ep = Ecb + (w * 32) * 4;
        const float* bp = sB + w * 32;
        #pragma unroll 2
        for (int j = 0; j < 32; j++) {
            uint4 q0 = ep[4 * j + 0];
            uint4 q1 = ep[4 * j + 1];
            uint4 q2 = ep[4 * j + 2];
            uint4 q3 = ep[4 * j + 3];
            int P0 = 0, P1 = 0;
            P0 = __dp4a((int)X0[0],  (int)q0.x, P0);
            P1 = __dp4a((int)X1[0],  (int)q0.x, P1);
            P0 = __dp4a((int)X0[1],  (int)q0.y, P0);
            P1 = __dp4a((int)X1[1],  (int)q0.y, P1);
            P0 = __dp4a((int)X0[2],  (int)q0.z, P0);
            P1 = __dp4a((int)X1[2],  (int)q0.z, P1);
            P0 = __dp4a((int)X0[3],  (int)q0.w, P0);
            P1 = __dp4a((int)X1[3],  (int)q0.w, P1);
            P0 = __dp4a((int)X0[4],  (int)q1.x, P0);
            P1 = __dp4a((int)X1[4],  (int)q1.x, P1);
            P0 = __dp4a((int)X0[5],  (int)q1.y, P0);
            P1 = __dp4a((int)X1[5],  (int)q1.y, P1);
            P0 = __dp4a((int)X0[6],  (int)q1.z, P0);
            P1 = __dp4a((int)X1[6],  (int)q1.z, P1);
            P0 = __dp4a((int)X0[7],  (int)q1.w, P0);
            P1 = __dp4a((int)X1[7],  (int)q1.w, P1);
            P0 = __dp4a((int)X0[8],  (int)q2.x, P0);
            P1 = __dp4a((int)X1[8],  (int)q2.x, P1);
            P0 = __dp4a((int)X0[9],  (int)q2.y, P0);
            P1 = __dp4a((int)X1[9],  (int)q2.y, P1);
            P0 = __dp4a((int)X0[10], (int)q2.z, P0);
            P1 = __dp4a((int)X1[10], (int)q2.z, P1);
            P0 = __dp4a((int)X0[11], (int)q2.w, P0);
            P1 = __dp4a((int)X1[11], (int)q2.w, P1);
            P0 = __dp4a((int)X0[12], (int)q3.x, P0);
            P1 = __dp4a((int)X1[12], (int)q3.x, P1);
            P0 = __dp4a((int)X0[13], (int)q3.y, P0);
            P1 = __dp4a((int)X1[13], (int)q3.y, P1);
            P0 = __dp4a((int)X0[14], (int)q3.z, P0);
            P1 = __dp4a((int)X1[14], (int)q3.z, P1);
            P0 = __dp4a((int)X0[15], (int)q3.w, P0);
            P1 = __dp4a((int)X1[15], (int)q3.w, P1);
            float bk = bp[j];
            float s0 = fmaf(c20, (float)P0, bk);
            float s1 = fmaf(c21, (float)P1, bk);
            m0  = (m0  >> 1) | ((s0 <= thr0) ? 0x80000000u : 0u);
            m1w = (m1w >> 1) | ((s1 <= thr1) ? 0x80000000u : 0u);
            thr0 = fminf(thr0, __fadd_rn(s0, mg0));
            thr1 = fminf(thr1, __fadd_rn(s1, mg1));
        }
        mrow0[w] = m0;
        mrow1[w] = m1w;
    }

    // ---- per pixel: exact refinement (bit-matches R2) + epilogue ----
    float sq = 0.0f;
    #pragma unroll 1
    for (int h = 0; h < 2; h++) {
        const float* px = h ? px1 : px0;
        const int n = h ? n1 : n0;
        const float A = h ? A1 : A0;
        const uint32_t* mrow = h ? mrow1 : mrow0;

        float x[DD];
        #pragma unroll
        for (int d = 0; d < DD; d++) x[d] = px[(size_t)d << 10];

        float best = CUDART_INF_F;
        int bi = 0;
        for (int w = 0; w < 16; w++) {
            uint32_t m = mrow[w];
            while (m) {
                int j = __ffs(m) - 1;
                m &= m - 1;
                int kk = w * 32 + j;
                const float4* e4p = (const float4*)(emb + kk * DD);
                float p = 0.0f;
                #pragma unroll
                for (int q = 0; q < DD / 4; q++) {
                    float4 e4 = e4p[q];
                    p = fmaf(e4.x, x[4 * q + 0], p);
                    p = fmaf(e4.y, x[4 * q + 1], p);
                    p = fmaf(e4.z, x[4 * q + 2], p);
                    p = fmaf(e4.w, x[4 * q + 3], p);
                }
                float dist = __fsub_rn(__fadd_rn(A, sB[kk]), __fmul_rn(2.0f, p));
                if (dist < best) { best = dist; bi = kk; }
            }
        }

        float* pout = out + 1 + (size_t)(n >> 10) * 65536 + (n & 1023);
        const float* qr = emb + bi * DD;
        #pragma unroll
        for (int d = 0; d < DD; d++) {
            float qd   = qr[d];
            float diff = __fsub_rn(qd, x[d]);
            sq = fmaf(diff, diff, sq);
            pout[(size_t)d << 10] = __fadd_rn(x[d], diff);
        }
        out[1 + (size_t)OUT_ELEMS + n] = (float)bi;
    }

    // ---- loss: block reduce -> per-CTA partial; last CTA finalizes ----
    __syncthreads();
    #pragma unroll
    for (int o = 16; o > 0; o >>= 1)
        sq += __shfl_down_sync(~0u, sq, o);
    if (lane == 0) scr[wid] = sq;
    __syncthreads();
    if (tid == 0) {
        float s = 0.0f;
        #pragma unroll
        for (int w = 0; w < 8; w++) s += scr[w];
        g_part[blockIdx.x] = s;
        __threadfence();
        unsigned int prev = atomicAdd(&g_cnt, 1u);
        if (prev == GRID - 1) {
            float tot = 0.0f;
            volatile float* gp = g_part;
            #pragma unroll
            for (int i = 0; i < GRID; i++) tot += gp[i];
            float mmean = tot * (1.0f / (float)OUT_ELEMS);
            out[0] = __fadd_rn(mmean, __fmul_rn(0.25f, mmean));
            g_cnt = 0u;
        }
    }
}

extern "C" void kernel_launch(void* const* d_in, const int* in_sizes, int n_in,
                              void* d_out, int out_size) {
    (void)in_sizes; (void)n_in; (void)out_size;
    cudaFuncSetAttribute(vq_main, cudaFuncAttributeMaxDynamicSharedMemorySize,
                         SMEM_TOTAL);
    vq_main<<<GRID, BLOCK, SMEM_TOTAL>>>((const float*)d_in[0],
                                         (const float*)d_in[1], (float*)d_out);
}

// round 11
// speedup vs baseline: 1.1574x; 1.1574x over previous
#include <cuda_runtime.h>
#include <math_constants.h>
#include <cstdint>

// VQ-VAE vector quantizer, GB300 (PTX sm_103). Round 10: int8 DP4A screening
// with the codebook in __constant__ memory (uniform constant port, bypassing
// the smem crossbar that bound R7) + exact fp32 refinement.
// Graph: prep kernel -> DtoD memcpy-to-symbol -> main kernel.
// inputs:  d_in[0] = inputs [64,64,32,32] fp32 NCHW, d_in[1] = emb_w [512,64] fp32
// output:  d_out fp32: loss[1] | out[4194304] NCHW | idx[65536]

#define DD        64
#define KK        512
#define NPIX      65536
#define BLOCK     512
#define GRID      128
#define OUT_ELEMS (NPIX * DD)

#define OFF_B    0                       // smem: [512] f32 ||e||^2 (refinement)
#define OFF_SCR  2048                    // 64 f32 scratch
#define OFF_MSK  2304                    // [512][17] u32 candidate masks
#define SMEM_TOTAL (OFF_MSK + BLOCK * 17 * 4)   // 37120 B

struct CData {
    uint4 E[KK * 4];    // int8-packed codebook rows, 64 B/code (32 KB)
    float B[KK];        // ||e_k||^2 (exact R1/R2 arithmetic order)
    float se;
    float L1emax;
    float pad[2];
};

__constant__ CData cD;
__device__   CData g_stage;
__device__   float g_part[GRID];
__device__   unsigned int g_cnt;         // zero-init; restored to 0 each run

// ---- prep: quantize codebook into staging (1 CTA, 512 threads) ----
__global__ __launch_bounds__(BLOCK, 1)
void vq_prep(const float* __restrict__ emb) {
    __shared__ float red[32];
    const int tid = threadIdx.x, wid = tid >> 5, lane = tid & 31;
    const float* er = emb + tid * DD;

    float Bk = 0.0f, L1e = 0.0f, mxe = 0.0f;
    #pragma unroll 8
    for (int d = 0; d < DD; d++) {
        float v = er[d];
        Bk = __fadd_rn(Bk, __fmul_rn(v, v));   // R1/R2-proven exact order
        float a = fabsf(v);
        L1e += a;
        mxe = fmaxf(mxe, a);
    }
    g_stage.B[tid] = Bk;

    float m1 = mxe, m2 = L1e;
    #pragma unroll
    for (int o = 16; o > 0; o >>= 1) {
        m1 = fmaxf(m1, __shfl_xor_sync(~0u, m1, o));
        m2 = fmaxf(m2, __shfl_xor_sync(~0u, m2, o));
    }
    if (lane == 0) { red[wid] = m1; red[16 + wid] = m2; }
    __syncthreads();
    float maxe = red[0], L1emax = red[16];
    #pragma unroll
    for (int w = 1; w < 16; w++) {
        maxe   = fmaxf(maxe,   red[w]);
        L1emax = fmaxf(L1emax, red[16 + w]);
    }
    maxe = fmaxf(maxe, 1e-30f);
    const float inv_se = 127.0f / maxe;

    uint32_t* Erow = (uint32_t*)&g_stage.E[tid * 4];
    #pragma unroll
    for (int i = 0; i < 16; i++) {
        int q0 = __float2int_rn(er[4 * i + 0] * inv_se);
        int q1 = __float2int_rn(er[4 * i + 1] * inv_se);
        int q2 = __float2int_rn(er[4 * i + 2] * inv_se);
        int q3 = __float2int_rn(er[4 * i + 3] * inv_se);
        Erow[i] = (uint32_t)(q0 & 0xFF) | ((uint32_t)(q1 & 0xFF) << 8) |
                  ((uint32_t)(q2 & 0xFF) << 16) | ((uint32_t)(q3 & 0xFF) << 24);
    }
    if (tid == 0) {
        g_stage.se     = maxe * (1.0f / 127.0f);
        g_stage.L1emax = L1emax;
    }
}

// ---- main ----
__global__ __launch_bounds__(BLOCK, 1)
void vq_main(const float* __restrict__ in, const float* __restrict__ emb,
             float* __restrict__ out) {
    extern __shared__ char smem[];
    float*    sB  = (float*)(smem + OFF_B);
    float*    scr = (float*)(smem + OFF_SCR);
    uint32_t* msk = (uint32_t*)(smem + OFF_MSK);
    const int tid = threadIdx.x, wid = tid >> 5, lane = tid & 31;

    // ||e||^2 into smem for the (non-uniform-indexed) refinement reads.
    sB[tid] = g_stage.B[tid];
    __syncthreads();

    const float se     = cD.se;
    const float L1emax = cD.L1emax;

    // ---- pixel stats (A in the proven R1 order, L1, max) ----
    const int n  = blockIdx.x * BLOCK + tid;
    const int b  = n >> 10;
    const int hw = n & 1023;
    const float* px = in + (size_t)b * 65536 + hw;

    float a0 = 0.f, a1 = 0.f, a2 = 0.f, a3 = 0.f, L1x = 0.f, mxx = 0.f;
    #pragma unroll
    for (int d = 0; d < DD; d += 4) {
        float v0 = px[(size_t)(d + 0) << 10];
        float v1 = px[(size_t)(d + 1) << 10];
        float v2 = px[(size_t)(d + 2) << 10];
        float v3 = px[(size_t)(d + 3) << 10];
        a0 = __fadd_rn(a0, __fmul_rn(v0, v0));
        a1 = __fadd_rn(a1, __fmul_rn(v1, v1));
        a2 = __fadd_rn(a2, __fmul_rn(v2, v2));
        a3 = __fadd_rn(a3, __fmul_rn(v3, v3));
        L1x += fabsf(v0) + fabsf(v1) + fabsf(v2) + fabsf(v3);
        mxx = fmaxf(mxx, fmaxf(fmaxf(fabsf(v0), fabsf(v1)),
                               fmaxf(fabsf(v2), fabsf(v3))));
    }
    const float A = __fadd_rn(__fadd_rn(a0, a2), __fadd_rn(a1, a3));
    mxx = fmaxf(mxx, 1e-30f);
    const float sx = mxx * (1.0f / 127.0f);
    const float inv_sx = 127.0f / mxx;

    uint32_t X[16];
    #pragma unroll
    for (int i = 0; i < 16; i++) {
        int q0 = __float2int_rn(px[(size_t)(4 * i + 0) << 10] * inv_sx);
        int q1 = __float2int_rn(px[(size_t)(4 * i + 1) << 10] * inv_sx);
        int q2 = __float2int_rn(px[(size_t)(4 * i + 2) << 10] * inv_sx);
        int q3 = __float2int_rn(px[(size_t)(4 * i + 3) << 10] * inv_sx);
        X[i] = (uint32_t)(q0 & 0xFF) | ((uint32_t)(q1 & 0xFF) << 8) |
               ((uint32_t)(q2 & 0xFF) << 16) | ((uint32_t)(q3 & 0xFF) << 24);
    }
    const float c2 = -2.0f * sx * se;
    const float margin = sx * L1emax + se * L1x + 16.0f * sx * se + 1e-6f; // 2*delta

    // ---- DP4A screening: B-operands from the constant port (uniform idx) ----
    float thr = CUDART_INF_F;
    uint32_t* mrow = msk + tid * 17;
    #pragma unroll 1
    for (int w = 0; w < 16; w++) {
        uint32_t m = 0;
        #pragma unroll 4
        for (int j = 0; j < 32; j++) {
            const uint4* ep = &cD.E[(w * 32 + j) * 4];
            uint4 q0 = ep[0];
            uint4 q1 = ep[1];
            uint4 q2 = ep[2];
            uint4 q3 = ep[3];
            int P = 0;
            P = __dp4a((int)X[0],  (int)q0.x, P);
            P = __dp4a((int)X[1],  (int)q0.y, P);
            P = __dp4a((int)X[2],  (int)q0.z, P);
            P = __dp4a((int)X[3],  (int)q0.w, P);
            P = __dp4a((int)X[4],  (int)q1.x, P);
            P = __dp4a((int)X[5],  (int)q1.y, P);
            P = __dp4a((int)X[6],  (int)q1.z, P);
            P = __dp4a((int)X[7],  (int)q1.w, P);
            P = __dp4a((int)X[8],  (int)q2.x, P);
            P = __dp4a((int)X[9],  (int)q2.y, P);
            P = __dp4a((int)X[10], (int)q2.z, P);
            P = __dp4a((int)X[11], (int)q2.w, P);
            P = __dp4a((int)X[12], (int)q3.x, P);
            P = __dp4a((int)X[13], (int)q3.y, P);
            P = __dp4a((int)X[14], (int)q3.z, P);
            P = __dp4a((int)X[15], (int)q3.w, P);
            float s = fmaf(c2, (float)P, cD.B[w * 32 + j]);
            m = (m >> 1) | ((s <= thr) ? 0x80000000u : 0u);  // bit j after 32
            thr = fminf(thr, __fadd_rn(s, margin));
        }
        mrow[w] = m;
    }

    // ---- exact refinement (bit-matches R2): ascending k, strict '<' ----
    float x[DD];
    #pragma unroll
    for (int d = 0; d < DD; d++) x[d] = px[(size_t)d << 10];
    float best = CUDART_INF_F;
    int bi = 0;
    for (int w = 0; w < 16; w++) {
        uint32_t m = mrow[w];
        while (m) {
            int j = __ffs(m) - 1;
            m &= m - 1;
            int kk = w * 32 + j;
            const float4* e4p = (const float4*)(emb + kk * DD);
            float p = 0.0f;
            #pragma unroll
            for (int q = 0; q < DD / 4; q++) {
                float4 e4 = e4p[q];
                p = fmaf(e4.x, x[4 * q + 0], p);
                p = fmaf(e4.y, x[4 * q + 1], p);
                p = fmaf(e4.z, x[4 * q + 2], p);
                p = fmaf(e4.w, x[4 * q + 3], p);
            }
            float dist = __fsub_rn(__fadd_rn(A, sB[kk]), __fmul_rn(2.0f, p));
            if (dist < best) { best = dist; bi = kk; }
        }
    }

    // ---- epilogue (bit-matches R2) ----
    float* pout = out + 1 + (size_t)b * 65536 + hw;
    const float* qr = emb + bi * DD;
    float sq = 0.0f;
    #pragma unroll
    for (int d = 0; d < DD; d++) {
        float qd   = qr[d];
        float diff = __fsub_rn(qd, x[d]);
        sq = fmaf(diff, diff, sq);
        pout[(size_t)d << 10] = __fadd_rn(x[d], diff);
    }
    out[1 + (size_t)OUT_ELEMS + n] = (float)bi;

    // ---- loss: block reduce -> per-CTA partial; last CTA finalizes ----
    __syncthreads();
    #pragma unroll
    for (int o = 16; o > 0; o >>= 1)
        sq += __shfl_down_sync(~0u, sq, o);
    if (lane == 0) scr[wid] = sq;
    __syncthreads();
    if (tid == 0) {
        float s = 0.0f;
        #pragma unroll
        for (int w = 0; w < 16; w++) s += scr[w];
        g_part[blockIdx.x] = s;
        __threadfence();
        unsigned int prev = atomicAdd(&g_cnt, 1u);
        if (prev == GRID - 1) {
            float tot = 0.0f;
            volatile float* gp = g_part;
            #pragma unroll
            for (int i = 0; i < GRID; i++) tot += gp[i];
            float mmean = tot * (1.0f / (float)OUT_ELEMS);
            out[0] = __fadd_rn(mmean, __fmul_rn(0.25f, mmean));
            g_cnt = 0u;
        }
    }
}

extern "C" void kernel_launch(void* const* d_in, const int* in_sizes, int n_in,
                              void* d_out, int out_size) {
    (void)in_sizes; (void)n_in; (void)out_size;
    const float* in  = (const float*)d_in[0];
    const float* emb = (const float*)d_in[1];
    float* out = (float*)d_out;

    cudaFuncSetAttribute(vq_main, cudaFuncAttributeMaxDynamicSharedMemorySize,
                         SMEM_TOTAL);
    void* stage_addr = nullptr;
    cudaGetSymbolAddress(&stage_addr, g_stage);

    vq_prep<<<1, BLOCK>>>(emb);
    cudaMemcpyToSymbolAsync(cD, stage_addr, sizeof(CData), 0,
                            cudaMemcpyDeviceToDevice, 0);
    vq_main<<<GRID, BLOCK, SMEM_TOTAL>>>(in, emb, out);
}

// round 12
// speedup vs baseline: 1.7060x; 1.4740x over previous
#include <cuda_runtime.h>
#include <math_constants.h>
#include <cstdint>

// VQ-VAE vector quantizer, GB300 (PTX sm_103). Round 12: R7 structure with a
// spill-free DP4A screening loop (unroll 2, dual 8-chains, low live-register
// count) + exact fp32 refinement. Single kernel, last-CTA loss finalize.
// inputs:  d_in[0] = inputs [64,64,32,32] fp32 NCHW, d_in[1] = emb_w [512,64] fp32
// output:  d_out fp32: loss[1] | out[4194304] NCHW | idx[65536]

#define DD        64
#define KK        512
#define NPIX      65536
#define BLOCK     512
#define GRID      128
#define OUT_ELEMS (NPIX * DD)

#define OFF_E    0                      // int8 codebook [512][64] = 32768 B
#define OFF_B    32768                  // [512] f32 ||e||^2
#define OFF_SCR  34816                  // 64 f32 scratch
#define OFF_MSK  35072                  // [512][17] u32 candidate masks
#define SMEM_TOTAL (OFF_MSK + BLOCK * 17 * 4)   // 69888 B

__device__ float g_part[GRID];
__device__ unsigned int g_cnt;          // zero-init; restored to 0 each run

__global__ __launch_bounds__(BLOCK, 1)
void vq_main(const float* __restrict__ in, const float* __restrict__ emb,
             float* __restrict__ out) {
    extern __shared__ char smem[];
    uint4*    Ecb = (uint4*)(smem + OFF_E);
    float*    sB  = (float*)(smem + OFF_B);
    float*    scr = (float*)(smem + OFF_SCR);
    uint32_t* msk = (uint32_t*)(smem + OFF_MSK);
    const int tid = threadIdx.x, wid = tid >> 5, lane = tid & 31;

    // ---- codebook prologue: thread t owns code t (BLOCK == KK) ----
    const float* er = emb + tid * DD;
    float Bk = 0.0f, L1e = 0.0f, mxe = 0.0f;
    #pragma unroll 8
    for (int d = 0; d < DD; d++) {
        float v = er[d];
        Bk = __fadd_rn(Bk, __fmul_rn(v, v));    // R1/R2-proven exact order
        float a = fabsf(v);
        L1e += a;
        mxe = fmaxf(mxe, a);
    }
    sB[tid] = Bk;
    float m1 = mxe, m2 = L1e;
    #pragma unroll
    for (int o = 16; o > 0; o >>= 1) {
        m1 = fmaxf(m1, __shfl_xor_sync(~0u, m1, o));
        m2 = fmaxf(m2, __shfl_xor_sync(~0u, m2, o));
    }
    if (lane == 0) { scr[wid] = m1; scr[16 + wid] = m2; }
    __syncthreads();
    float maxe = scr[0], L1emax = scr[16];
    #pragma unroll
    for (int w = 1; w < 16; w++) {
        maxe   = fmaxf(maxe,   scr[w]);
        L1emax = fmaxf(L1emax, scr[16 + w]);
    }
    maxe = fmaxf(maxe, 1e-30f);
    const float se = maxe * (1.0f / 127.0f);
    const float inv_se = 127.0f / maxe;
    {   // quantize + pack own code row: [64] int8 -> 16 u32
        uint32_t* Erow = (uint32_t*)(Ecb + tid * 4);
        #pragma unroll
        for (int i = 0; i < 16; i++) {
            int q0 = __float2int_rn(er[4 * i + 0] * inv_se);
            int q1 = __float2int_rn(er[4 * i + 1] * inv_se);
            int q2 = __float2int_rn(er[4 * i + 2] * inv_se);
            int q3 = __float2int_rn(er[4 * i + 3] * inv_se);
            Erow[i] = (uint32_t)(q0 & 0xFF) | ((uint32_t)(q1 & 0xFF) << 8) |
                      ((uint32_t)(q2 & 0xFF) << 16) | ((uint32_t)(q3 & 0xFF) << 24);
        }
    }
    __syncthreads();

    // ---- pixel stats (A in the proven R1 order, L1, max) ----
    const int n  = blockIdx.x * BLOCK + tid;
    const int b  = n >> 10;
    const int hw = n & 1023;
    const float* px = in + (size_t)b * 65536 + hw;

    float a0 = 0.f, a1 = 0.f, a2 = 0.f, a3 = 0.f, L1x = 0.f, mxx = 0.f;
    #pragma unroll
    for (int d = 0; d < DD; d += 4) {
        float v0 = px[(size_t)(d + 0) << 10];
        float v1 = px[(size_t)(d + 1) << 10];
        float v2 = px[(size_t)(d + 2) << 10];
        float v3 = px[(size_t)(d + 3) << 10];
        a0 = __fadd_rn(a0, __fmul_rn(v0, v0));
        a1 = __fadd_rn(a1, __fmul_rn(v1, v1));
        a2 = __fadd_rn(a2, __fmul_rn(v2, v2));
        a3 = __fadd_rn(a3, __fmul_rn(v3, v3));
        L1x += fabsf(v0) + fabsf(v1) + fabsf(v2) + fabsf(v3);
        mxx = fmaxf(mxx, fmaxf(fmaxf(fabsf(v0), fabsf(v1)),
                               fmaxf(fabsf(v2), fabsf(v3))));
    }
    const float A = __fadd_rn(__fadd_rn(a0, a2), __fadd_rn(a1, a3));
    mxx = fmaxf(mxx, 1e-30f);
    const float sx = mxx * (1.0f / 127.0f);
    const float inv_sx = 127.0f / mxx;

    uint32_t X[16];
    #pragma unroll
    for (int i = 0; i < 16; i++) {
        int q0 = __float2int_rn(px[(size_t)(4 * i + 0) << 10] * inv_sx);
        int q1 = __float2int_rn(px[(size_t)(4 * i + 1) << 10] * inv_sx);
        int q2 = __float2int_rn(px[(size_t)(4 * i + 2) << 10] * inv_sx);
        int q3 = __float2int_rn(px[(size_t)(4 * i + 3) << 10] * inv_sx);
        X[i] = (uint32_t)(q0 & 0xFF) | ((uint32_t)(q1 & 0xFF) << 8) |
               ((uint32_t)(q2 & 0xFF) << 16) | ((uint32_t)(q3 & 0xFF) << 24);
    }
    const float c2 = -2.0f * sx * se;
    const float margin = sx * L1emax + se * L1x + 16.0f * sx * se + 1e-6f; // 2*delta

    // ---- DP4A screening (spill-free): unroll 2, dual 8-chains per code ----
    float thr = CUDART_INF_F;
    uint32_t* mrow = msk + tid * 17;
    #pragma unroll 1
    for (int w = 0; w < 16; w++) {
        uint32_t m = 0;
        const uint4* ep = Ecb + (w * 32) * 4;
        const float* bp = sB + w * 32;
        #pragma unroll 2
        for (int j = 0; j < 32; j++) {
            uint4 qa = ep[4 * j + 0];
            uint4 qb = ep[4 * j + 1];
            int Pa = 0, Pb = 0;
            Pa = __dp4a((int)X[0],  (int)qa.x, Pa);
            Pa = __dp4a((int)X[1],  (int)qa.y, Pa);
            Pa = __dp4a((int)X[2],  (int)qa.z, Pa);
            Pa = __dp4a((int)X[3],  (int)qa.w, Pa);
            Pa = __dp4a((int)X[4],  (int)qb.x, Pa);
            Pa = __dp4a((int)X[5],  (int)qb.y, Pa);
            Pa = __dp4a((int)X[6],  (int)qb.z, Pa);
            Pa = __dp4a((int)X[7],  (int)qb.w, Pa);
            uint4 qc = ep[4 * j + 2];
            uint4 qd = ep[4 * j + 3];
            Pb = __dp4a((int)X[8],  (int)qc.x, Pb);
            Pb = __dp4a((int)X[9],  (int)qc.y, Pb);
            Pb = __dp4a((int)X[10], (int)qc.z, Pb);
            Pb = __dp4a((int)X[11], (int)qc.w, Pb);
            Pb = __dp4a((int)X[12], (int)qd.x, Pb);
            Pb = __dp4a((int)X[13], (int)qd.y, Pb);
            Pb = __dp4a((int)X[14], (int)qd.z, Pb);
            Pb = __dp4a((int)X[15], (int)qd.w, Pb);
            float s = fmaf(c2, (float)(Pa + Pb), bp[j]);
            m = (m >> 1) | ((s <= thr) ? 0x80000000u : 0u);  // bit j after 32
            thr = fminf(thr, __fadd_rn(s, margin));
        }
        mrow[w] = m;
    }

    // ---- exact refinement (bit-matches R2): ascending k, strict '<' ----
    float x[DD];
    #pragma unroll
    for (int d = 0; d < DD; d++) x[d] = px[(size_t)d << 10];
    float best = CUDART_INF_F;
    int bi = 0;
    for (int w = 0; w < 16; w++) {
        uint32_t m = mrow[w];
        while (m) {
            int j = __ffs(m) - 1;
            m &= m - 1;
            int kk = w * 32 + j;
            const float4* e4p = (const float4*)(emb + kk * DD);
            float p = 0.0f;
            #pragma unroll
            for (int q = 0; q < DD / 4; q++) {
                float4 e4 = e4p[q];
                p = fmaf(e4.x, x[4 * q + 0], p);
                p = fmaf(e4.y, x[4 * q + 1], p);
                p = fmaf(e4.z, x[4 * q + 2], p);
                p = fmaf(e4.w, x[4 * q + 3], p);
            }
            float dist = __fsub_rn(__fadd_rn(A, sB[kk]), __fmul_rn(2.0f, p));
            if (dist < best) { best = dist; bi = kk; }
        }
    }

    // ---- epilogue (bit-matches R2) ----
    float* pout = out + 1 + (size_t)b * 65536 + hw;
    const float* qr = emb + bi * DD;
    float sq = 0.0f;
    #pragma unroll
    for (int d = 0; d < DD; d++) {
        float qd   = qr[d];
        float diff = __fsub_rn(qd, x[d]);
        sq = fmaf(diff, diff, sq);
        pout[(size_t)d << 10] = __fadd_rn(x[d], diff);
    }
    out[1 + (size_t)OUT_ELEMS + n] = (float)bi;

    // ---- loss: block reduce -> per-CTA partial; last CTA finalizes ----
    __syncthreads();
    #pragma unroll
    for (int o = 16; o > 0; o >>= 1)
        sq += __shfl_down_sync(~0u, sq, o);
    if (lane == 0) scr[wid] = sq;
    __syncthreads();
    if (tid == 0) {
        float s = 0.0f;
        #pragma unroll
        for (int w = 0; w < 16; w++) s += scr[w];
        g_part[blockIdx.x] = s;
        __threadfence();
        unsigned int prev = atomicAdd(&g_cnt, 1u);
        if (prev == GRID - 1) {
            float tot = 0.0f;
            volatile float* gp = g_part;
            #pragma unroll
            for (int i = 0; i < GRID; i++) tot += gp[i];
            float mmean = tot * (1.0f / (float)OUT_ELEMS);
            out[0] = __fadd_rn(mmean, __fmul_rn(0.25f, mmean));
            g_cnt = 0u;
        }
    }
}

extern "C" void kernel_launch(void* const* d_in, const int* in_sizes, int n_in,
                              void* d_out, int out_size) {
    (void)in_sizes; (void)n_in; (void)out_size;
    cudaFuncSetAttribute(vq_main, cudaFuncAttributeMaxDynamicSharedMemorySize,
                         SMEM_TOTAL);
    vq_main<<<GRID, BLOCK, SMEM_TOTAL>>>((const float*)d_in[0],
                                         (const float*)d_in[1], (float*)d_out);
}